// round 5
// baseline (speedup 1.0000x reference)
#include <cuda_runtime.h>
#include <cuda_bf16.h>

// out[bt, i*16 + j] = x[bt, i] * W[i, j] + b[i, j]
// 256 MB fp32 output write stream. R1-R4: four disjoint store paths all hit
// ~4.4 TB/s ncu-HBM. This round: maximize store burst depth -- 4 independent
// LDG -> 32 FMA -> 4 independent STG.256 per thread per iteration, with a grid
// that divides the work exactly (no tail, no bounds checks).

#define C_IN   128
#define C_OUT  16
#define NBT    (64 * 512)
#define TOTAL_F8 (8388608u)          // NBT * 2048 / 8 = 2^23

#define NBLOCKS 1024
#define NTHREADS 256
#define STRIDE  (NBLOCKS * NTHREADS)         // 2^18 f8 per step
#define OUTER   (TOTAL_F8 / (STRIDE * 4))    // 8 outer iterations, 4-way unrolled

__global__ __launch_bounds__(NTHREADS, 8)
void real_embedding_kernel(const float* __restrict__ x,
                           const float* __restrict__ W,
                           const float* __restrict__ b,
                           float* __restrict__ out)
{
    const unsigned tid0 = blockIdx.x * NTHREADS + threadIdx.x;

    // stride is a multiple of 256 f8 -> per-thread (i, h) loop-invariant.
    const unsigned h = tid0 & 1u;            // which 8-float half of the 16 outputs
    const unsigned i = (tid0 >> 1) & 127u;   // input feature

    const float4* W4 = (const float4*)(W + i * C_OUT + h * 8);
    const float4* B4 = (const float4*)(b + i * C_OUT + h * 8);
    const float4 w0 = W4[0], w1 = W4[1];
    const float4 c0 = B4[0], c1 = B4[1];

    const unsigned bt_step = STRIDE >> 8;    // 1024 bt per stride step
    unsigned bt  = tid0 >> 8;
    unsigned gid = tid0;

#pragma unroll 1
    for (unsigned o = 0; o < OUTER; o++) {
        // 4 independent x loads (front-batched -> MLP 4)
        const float xv0 = __ldg(x + (size_t)(bt)               * C_IN + i);
        const float xv1 = __ldg(x + (size_t)(bt +     bt_step) * C_IN + i);
        const float xv2 = __ldg(x + (size_t)(bt + 2 * bt_step) * C_IN + i);
        const float xv3 = __ldg(x + (size_t)(bt + 3 * bt_step) * C_IN + i);

        float r0[8], r1[8], r2[8], r3[8];
        r0[0]=fmaf(xv0,w0.x,c0.x); r0[1]=fmaf(xv0,w0.y,c0.y); r0[2]=fmaf(xv0,w0.z,c0.z); r0[3]=fmaf(xv0,w0.w,c0.w);
        r0[4]=fmaf(xv0,w1.x,c1.x); r0[5]=fmaf(xv0,w1.y,c1.y); r0[6]=fmaf(xv0,w1.z,c1.z); r0[7]=fmaf(xv0,w1.w,c1.w);
        r1[0]=fmaf(xv1,w0.x,c0.x); r1[1]=fmaf(xv1,w0.y,c0.y); r1[2]=fmaf(xv1,w0.z,c0.z); r1[3]=fmaf(xv1,w0.w,c0.w);
        r1[4]=fmaf(xv1,w1.x,c1.x); r1[5]=fmaf(xv1,w1.y,c1.y); r1[6]=fmaf(xv1,w1.z,c1.z); r1[7]=fmaf(xv1,w1.w,c1.w);
        r2[0]=fmaf(xv2,w0.x,c0.x); r2[1]=fmaf(xv2,w0.y,c0.y); r2[2]=fmaf(xv2,w0.z,c0.z); r2[3]=fmaf(xv2,w0.w,c0.w);
        r2[4]=fmaf(xv2,w1.x,c1.x); r2[5]=fmaf(xv2,w1.y,c1.y); r2[6]=fmaf(xv2,w1.z,c1.z); r2[7]=fmaf(xv2,w1.w,c1.w);
        r3[0]=fmaf(xv3,w0.x,c0.x); r3[1]=fmaf(xv3,w0.y,c0.y); r3[2]=fmaf(xv3,w0.z,c0.z); r3[3]=fmaf(xv3,w0.w,c0.w);
        r3[4]=fmaf(xv3,w1.x,c1.x); r3[5]=fmaf(xv3,w1.y,c1.y); r3[6]=fmaf(xv3,w1.z,c1.z); r3[7]=fmaf(xv3,w1.w,c1.w);

        // 4 independent 256-bit stores, back-to-back (128B burst per thread).
        float* d0 = out + (size_t)(gid)              * 8;
        float* d1 = out + (size_t)(gid +     STRIDE) * 8;
        float* d2 = out + (size_t)(gid + 2 * STRIDE) * 8;
        float* d3 = out + (size_t)(gid + 3 * STRIDE) * 8;
        asm volatile("st.global.v8.f32 [%0], {%1,%2,%3,%4,%5,%6,%7,%8};" ::
            "l"(d0), "f"(r0[0]),"f"(r0[1]),"f"(r0[2]),"f"(r0[3]),
                     "f"(r0[4]),"f"(r0[5]),"f"(r0[6]),"f"(r0[7]) : "memory");
        asm volatile("st.global.v8.f32 [%0], {%1,%2,%3,%4,%5,%6,%7,%8};" ::
            "l"(d1), "f"(r1[0]),"f"(r1[1]),"f"(r1[2]),"f"(r1[3]),
                     "f"(r1[4]),"f"(r1[5]),"f"(r1[6]),"f"(r1[7]) : "memory");
        asm volatile("st.global.v8.f32 [%0], {%1,%2,%3,%4,%5,%6,%7,%8};" ::
            "l"(d2), "f"(r2[0]),"f"(r2[1]),"f"(r2[2]),"f"(r2[3]),
                     "f"(r2[4]),"f"(r2[5]),"f"(r2[6]),"f"(r2[7]) : "memory");
        asm volatile("st.global.v8.f32 [%0], {%1,%2,%3,%4,%5,%6,%7,%8};" ::
            "l"(d3), "f"(r3[0]),"f"(r3[1]),"f"(r3[2]),"f"(r3[3]),
                     "f"(r3[4]),"f"(r3[5]),"f"(r3[6]),"f"(r3[7]) : "memory");

        gid += 4 * STRIDE;
        bt  += 4 * bt_step;
    }
}

extern "C" void kernel_launch(void* const* d_in, const int* in_sizes, int n_in,
                              void* d_out, int out_size) {
    const float* x = (const float*)d_in[0];
    const float* W = (const float*)d_in[1];
    const float* b = (const float*)d_in[2];
    float* out = (float*)d_out;

    (void)in_sizes; (void)n_in; (void)out_size;

    real_embedding_kernel<<<NBLOCKS, NTHREADS>>>(x, W, b, out);
}